// round 17
// baseline (speedup 1.0000x reference)
#include <cuda_runtime.h>
#include <cuda_bf16.h>
#include <cstdint>

// Output = one_hot(arange(N), N) @ W = I @ W = W: an 8 MiB D2D copy.
//
// Session model (15 rounds, 12 implementations): wallclock ~6.6-6.9us =
// idle-DVFS serial chain (launch/dispatch + one memory round-trip) +
// mandatory 16 MiB L2 traffic at down-clocked fabric + ~0.5-0.9us graph
// replay. Invariant to request path, cache ops, vector width, MLP depth.
//
// Last untested cell in the sweep matrix: maximal-width CTAs at minimal
// grid. 128 CTAs x 1024 threads x 4 vec4 = 524288 vec4 = 8 MiB exact.
// 4x fewer CTAs to dispatch than the 512-CTA best config, one CTA per SM
// with all 32 warps resident after a single dispatch -> attacks the only
// remaining variable term (dispatch serialization at idle clock). Warp-
// level shape unchanged: 4 independent front-batched LDG.128, coalesced
// 128B lines, no loops/bounds checks.

__global__ void __launch_bounds__(1024) copy_w_wide(const float4* __restrict__ src,
                                                    float4* __restrict__ dst) {
    // CTA tile = 4096 vec4 (64 KiB); thread t handles {base+t, +1024,
    // +2048, +3072}. Every warp access is one contiguous 128B line.
    int base = blockIdx.x * (1024 * 4) + threadIdx.x;

    float4 a0 = src[base + 0 * 1024];
    float4 a1 = src[base + 1 * 1024];
    float4 a2 = src[base + 2 * 1024];
    float4 a3 = src[base + 3 * 1024];

    dst[base + 0 * 1024] = a0;
    dst[base + 1 * 1024] = a1;
    dst[base + 2 * 1024] = a2;
    dst[base + 3 * 1024] = a3;
}

extern "C" void kernel_launch(void* const* d_in, const int* in_sizes, int n_in,
                              void* d_out, int out_size) {
    const float4* W = (const float4*)d_in[0];
    float4* out = (float4*)d_out;
    // out_size = 16384*128 = 2097152 floats = 524288 vec4 -> 128 CTAs exact.
    int blocks = out_size / (4 * 1024 * 4);
    copy_w_wide<<<blocks, 1024>>>(W, out);
}